// round 15
// baseline (speedup 1.0000x reference)
#include <cuda_runtime.h>
#include <cuda_bf16.h>
#include <cstdint>

// B=16, T=4096 -> N=65536 tokens, D=64, K=1024
#define D 64
#define K 1024
#define BMT 128          // tokens per CTA
#define CHN 64           // codes per sub-chunk (acc = 32 regs)
#define NCS 16           // 16 sub-chunks; barrier every 2
#define THREADS 256      // 8 warps, all M (16 token rows each)
#define CAP 32           // candidate list capacity per token
#define EPS_C 0.0170f    // >= 2*(2*2^-8+2^-16) + slack

#define ATILE_BYTES 16384            // 128 rows x 128 B bf16, SW128
#define BSUB_BYTES  8192             // 64 rows x 128 B
#define OFF_H    0                   // K floats (4 KB)
#define OFF_N2   4096                // ||x||^2 per row (512 B)
#define OFF_CNT  4608                // candidate counts (512 B)
#define OFF_SI   5120                // final index (512 B)
#define OFF_CAND 5632                // 128 x CAP ints (16 KB)
#define OFF_A    22528               // x0 tile (16 KB), 1024-aligned
#define OFF_B    38912               // 2 buffers x 16 KB (2 sub-tiles each)
#define SMEM_TOTAL (OFF_B + 2 * 16384)   // 71680 B = 70 KB -> 3 CTAs/SM

#define SWZ(b) ((b) ^ (((b) >> 3) & 0x70))

__device__ float          g_embedT[K * D];   // [k][d] fp32 (gather + exact eval)
__device__ float          g_h[K];            // 0.5 * ||e_k||^2
__device__ __nv_bfloat16  g_e0[K * D];       // [k][d] bf16 hi split
__device__ int            g_emax_bits = 0;   // max ||e_k|| as float bits

__device__ __forceinline__ void cp16(uint32_t s, const void* g) {
    asm volatile("cp.async.cg.shared.global [%0], [%1], 16;" :: "r"(s), "l"(g));
}
#define CP_COMMIT()  asm volatile("cp.async.commit_group;")
#define CP_WAIT0()   asm volatile("cp.async.wait_group 0;")

__device__ __forceinline__ void ldsm4(uint32_t r[4], uint32_t addr) {
    asm volatile("ldmatrix.sync.aligned.m8n8.x4.shared.b16 {%0,%1,%2,%3}, [%4];"
        : "=r"(r[0]), "=r"(r[1]), "=r"(r[2]), "=r"(r[3]) : "r"(addr));
}
__device__ __forceinline__ void mma16816(float c[4], const uint32_t a[4],
                                         uint32_t b0, uint32_t b1) {
    asm volatile("mma.sync.aligned.m16n8k16.row.col.f32.bf16.bf16.f32 "
        "{%0,%1,%2,%3}, {%4,%5,%6,%7}, {%8,%9}, {%0,%1,%2,%3};"
        : "+f"(c[0]), "+f"(c[1]), "+f"(c[2]), "+f"(c[3])
        : "r"(a[0]), "r"(a[1]), "r"(a[2]), "r"(a[3]), "r"(b0), "r"(b1));
}
__device__ __forceinline__ uint32_t pack_bf16x2(__nv_bfloat16 lo, __nv_bfloat16 hi) {
    return (uint32_t)__bfloat16_as_ushort(lo) | ((uint32_t)__bfloat16_as_ushort(hi) << 16);
}

// ------------- prep: hi split [k][d], transpose, norms, max-norm -------------
__global__ void vq_prep(const float* __restrict__ embed) {
    int i = blockIdx.x * blockDim.x + threadIdx.x;
    if (i < K * D) {
        int k = i >> 6;
        int d = i & 63;
        float v = embed[d * K + k];
        g_embedT[i] = v;
        g_e0[i] = __float2bfloat16(v);
    }
    if (i < K) {
        float s = 0.f;
        #pragma unroll
        for (int d = 0; d < D; d++) {
            float v = embed[d * K + i];
            s = fmaf(v, v, s);
        }
        g_h[i] = 0.5f * s;
        atomicMax(&g_emax_bits, __float_as_int(sqrtf(s)));
    }
}

__device__ __forceinline__ float score_exact(const float4* x4, int k, const float* hs) {
    const float4* e4 = (const float4*)(g_embedT + k * D);
    float dot = 0.f;
    #pragma unroll
    for (int i = 0; i < 16; i++) {
        float4 a = x4[i], b = e4[i];
        dot = fmaf(a.x, b.x, dot);
        dot = fmaf(a.y, b.y, dot);
        dot = fmaf(a.z, b.z, dot);
        dot = fmaf(a.w, b.w, dot);
    }
    return hs[k] - dot;
}

// ------------- main: hi-split HMMA + streaming prune + exact verify -------------
__global__ __launch_bounds__(THREADS, 3)
void vq_main(const float* __restrict__ input,
             float* __restrict__ q_out,
             float* __restrict__ diff_out,
             float* __restrict__ ind_out) {
    extern __shared__ char smem[];
    const uint32_t sb = (uint32_t)__cvta_generic_to_shared(smem);
    float* hs   = (float*)(smem + OFF_H);
    float* n2   = (float*)(smem + OFF_N2);
    int*   cnt  = (int*)(smem + OFF_CNT);
    int*   s_ix = (int*)(smem + OFF_SI);
    int*   cand = (int*)(smem + OFF_CAND);

    const int tid  = threadIdx.x;
    const int wid  = tid >> 5;     // 0..7 : token rows 16*wid
    const int lane = tid & 31;
    const int n0   = blockIdx.x * BMT;

    if (tid < BMT) cnt[tid] = 0;

    // ---- prologue: x -> bf16 hi tile (SW128) + ||x||^2 via shuffle reduce ----
    const float4* in4 = reinterpret_cast<const float4*>(input + (size_t)n0 * D);
    #pragma unroll
    for (int t = 0; t < 8; t++) {
        int idx = t * THREADS + tid;       // 0..2047 float4
        float4 v = in4[idx];
        int row = idx >> 4;
        int c   = (idx & 15) << 2;
        float p = v.x * v.x + v.y * v.y + v.z * v.z + v.w * v.w;
        #pragma unroll
        for (int m = 1; m <= 8; m <<= 1)
            p += __shfl_xor_sync(0xffffffffu, p, m);   // 16-lane group sum
        if ((tid & 15) == 0) n2[row] = p;
        uint32_t off = SWZ((uint32_t)(row * 128 + c * 2));
        *(uint32_t*)(smem + OFF_A + off)     = pack_bf16x2(__float2bfloat16(v.x), __float2bfloat16(v.y));
        *(uint32_t*)(smem + OFF_A + off + 4) = pack_bf16x2(__float2bfloat16(v.z), __float2bfloat16(v.w));
    }
    #pragma unroll
    for (int t = tid; t < K; t += THREADS) hs[t] = g_h[t];

    // ---- prefetch codes 0..127 (2 sub-tiles): 1024 granules ----
    #pragma unroll
    for (int i = 0; i < 4; i++) {
        int idx = i * THREADS + tid;
        int row = idx >> 3, g = idx & 7;
        cp16(sb + OFF_B + (uint32_t)((row >> 6) * BSUB_BYTES)
                 + SWZ((uint32_t)((row & 63) * 128 + g * 16)),
             g_e0 + (size_t)row * 64 + g * 8);
    }
    CP_COMMIT();

    const float emax = __int_as_float(g_emax_bits);

    const int l7      = lane & 7;
    const int aRowSel = ((lane >> 3) & 1) << 3;
    const int aKSel   = (lane >> 4) << 4;
    const int bRowSel = (lane >> 4) << 3;
    const int bKSel   = ((lane >> 3) & 1) << 4;

    __syncthreads();   // A tile + hs + n2 visible

    // ---- A fragments (chunk-invariant, 16 regs) ----
    uint32_t afr[4][4];
    #pragma unroll
    for (int ks = 0; ks < 4; ks++)
        ldsm4(afr[ks], sb + (uint32_t)OFF_A
            + SWZ((uint32_t)((wid * 16 + aRowSel + l7) * 128 + ks * 32 + aKSel)));

    const int row0 = wid * 16 + (lane >> 2);
    const int row1 = row0 + 8;
    const float eps0 = EPS_C * sqrtf(n2[row0]) * emax;
    const float eps1 = EPS_C * sqrtf(n2[row1]) * emax;

    float rb0 = 3.4e38f, rb1 = 3.4e38f;   // running prefix min per row
    float th0 = 3.4e38f, th1 = 3.4e38f;   // lagged thresholds

    for (int cs = 0; cs < NCS; cs++) {
        if ((cs & 1) == 0) {
            CP_WAIT0();
            __syncthreads();   // staged; everyone done with the other buffer
            if (cs + 2 < NCS) {
                int kb = (cs + 2) * CHN;
                uint32_t bufo = (uint32_t)(OFF_B + (((cs >> 1) + 1) & 1) * 16384);
                #pragma unroll
                for (int i = 0; i < 4; i++) {
                    int idx = i * THREADS + tid;
                    int row = idx >> 3, g = idx & 7;
                    cp16(sb + bufo + (uint32_t)((row >> 6) * BSUB_BYTES)
                             + SWZ((uint32_t)((row & 63) * 128 + g * 16)),
                         g_e0 + (size_t)(kb + row) * 64 + g * 8);
                }
                CP_COMMIT();
            }
        }

        const uint32_t bbase = sb + (uint32_t)(OFF_B + ((cs >> 1) & 1) * 16384
                                               + (cs & 1) * BSUB_BYTES);

        float acc[8][4];
        #pragma unroll
        for (int j = 0; j < 8; j++)
            #pragma unroll
            for (int q = 0; q < 4; q++) acc[j][q] = 0.f;

        #pragma unroll
        for (int ks = 0; ks < 4; ks++) {
            uint32_t bf[4][4];
            #pragma unroll
            for (int jj = 0; jj < 4; jj++)
                ldsm4(bf[jj], bbase
                    + SWZ((uint32_t)((jj * 16 + bRowSel + l7) * 128 + ks * 32 + bKSel)));
            #pragma unroll
            for (int jj = 0; jj < 4; jj++) {
                mma16816(acc[jj * 2 + 0], afr[ks], bf[jj][0], bf[jj][1]);
                mma16816(acc[jj * 2 + 1], afr[ks], bf[jj][2], bf[jj][3]);
            }
        }

        float m0 = 3.4e38f, m1 = 3.4e38f;
        if (cs == 0) {
            #pragma unroll
            for (int j = 0; j < 8; j++) {
                int k0 = j * 8 + (lane & 3) * 2;
                float2 hv = *(const float2*)&hs[k0];
                acc[j][0] = hv.x - acc[j][0];
                acc[j][1] = hv.y - acc[j][1];
                acc[j][2] = hv.x - acc[j][2];
                acc[j][3] = hv.y - acc[j][3];
                m0 = fminf(m0, fminf(acc[j][0], acc[j][1]));
                m1 = fminf(m1, fminf(acc[j][2], acc[j][3]));
            }
            #pragma unroll
            for (int m = 1; m <= 2; m <<= 1) {
                m0 = fminf(m0, __shfl_xor_sync(0xffffffffu, m0, m));
                m1 = fminf(m1, __shfl_xor_sync(0xffffffffu, m1, m));
            }
            rb0 = m0; rb1 = m1;
            th0 = rb0 + eps0; th1 = rb1 + eps1;
            #pragma unroll
            for (int j = 0; j < 8; j++) {
                int k0 = j * 8 + (lane & 3) * 2;
                if (acc[j][0] < th0) { int p = atomicAdd(&cnt[row0], 1); if (p < CAP) cand[row0 * CAP + p] = k0; }
                if (acc[j][1] < th0) { int p = atomicAdd(&cnt[row0], 1); if (p < CAP) cand[row0 * CAP + p] = k0 + 1; }
                if (acc[j][2] < th1) { int p = atomicAdd(&cnt[row1], 1); if (p < CAP) cand[row1 * CAP + p] = k0; }
                if (acc[j][3] < th1) { int p = atomicAdd(&cnt[row1], 1); if (p < CAP) cand[row1 * CAP + p] = k0 + 1; }
            }
        } else {
            // fused: collect with lagged threshold (prefix >= final -> superset)
            #pragma unroll
            for (int j = 0; j < 8; j++) {
                int k0 = cs * CHN + j * 8 + (lane & 3) * 2;
                float2 hv = *(const float2*)&hs[k0];
                float s0 = hv.x - acc[j][0];
                float s1 = hv.y - acc[j][1];
                float s2 = hv.x - acc[j][2];
                float s3 = hv.y - acc[j][3];
                m0 = fminf(m0, fminf(s0, s1));
                m1 = fminf(m1, fminf(s2, s3));
                if (s0 < th0) { int p = atomicAdd(&cnt[row0], 1); if (p < CAP) cand[row0 * CAP + p] = k0; }
                if (s1 < th0) { int p = atomicAdd(&cnt[row0], 1); if (p < CAP) cand[row0 * CAP + p] = k0 + 1; }
                if (s2 < th1) { int p = atomicAdd(&cnt[row1], 1); if (p < CAP) cand[row1 * CAP + p] = k0; }
                if (s3 < th1) { int p = atomicAdd(&cnt[row1], 1); if (p < CAP) cand[row1 * CAP + p] = k0 + 1; }
            }
            #pragma unroll
            for (int m = 1; m <= 2; m <<= 1) {
                m0 = fminf(m0, __shfl_xor_sync(0xffffffffu, m0, m));
                m1 = fminf(m1, __shfl_xor_sync(0xffffffffu, m1, m));
            }
            rb0 = fminf(rb0, m0);
            rb1 = fminf(rb1, m1);
            th0 = rb0 + eps0;
            th1 = rb1 + eps1;
        }
    }

    __syncthreads();

    // ---- exact verification: fp32 re-eval of candidates per token ----
    if (tid < BMT) {
        int row = tid;
        const float4* x4 = (const float4*)(input + (size_t)(n0 + row) * D);
        int n = cnt[row];
        float bsv = 3.4e38f;
        int   bix = 0;
        if (n <= CAP) {
            for (int j = 0; j < n; j++) {
                int k = cand[row * CAP + j];
                float s = score_exact(x4, k, hs);
                if (s < bsv || (s == bsv && k < bix)) { bsv = s; bix = k; }
            }
        } else {
            for (int k = 0; k < K; k++) {   // overflow fallback: exact scan
                float s = score_exact(x4, k, hs);
                if (s < bsv) { bsv = s; bix = k; }
            }
        }
        s_ix[row] = bix;
        if (ind_out) ind_out[n0 + row] = (float)bix;
    }
    __syncthreads();

    // ---- gather quantize + diff (coalesced float4) ----
    #pragma unroll
    for (int t = 0; t < 8; t++) {
        int idx = t * THREADS + tid;
        int row = idx >> 4;
        int cc  = (idx & 15) << 2;
        int kq  = s_ix[row];
        float4 q = *(const float4*)(g_embedT + kq * D + cc);
        float4 x = in4[idx];
        size_t o = (size_t)(n0 + row) * D + cc;
        *reinterpret_cast<float4*>(&q_out[o]) = q;
        if (diff_out) {
            float4 df;
            df.x = (q.x - x.x) * (q.x - x.x);
            df.y = (q.y - x.y) * (q.y - x.y);
            df.z = (q.z - x.z) * (q.z - x.z);
            df.w = (q.w - x.w) * (q.w - x.w);
            *reinterpret_cast<float4*>(&diff_out[o]) = df;
        }
    }
}

extern "C" void kernel_launch(void* const* d_in, const int* in_sizes, int n_in,
                              void* d_out, int out_size) {
    const float* input = (const float*)d_in[0];   // [B,T,D] fp32
    const float* embed = (const float*)d_in[1];   // [D,K]   fp32

    const int N = in_sizes[0] / D;
    const long nd = (long)N * D;

    float* out = (float*)d_out;
    float* q_out    = out;
    float* diff_out = nullptr;
    float* ind_out  = nullptr;
    if ((long)out_size >= 2 * nd + N) { diff_out = out + nd; ind_out = out + 2 * nd; }
    else if ((long)out_size >= 2 * nd) { diff_out = out + nd; }

    cudaFuncSetAttribute(vq_main, cudaFuncAttributeMaxDynamicSharedMemorySize, SMEM_TOTAL);

    vq_prep<<<(K * D + 255) / 256, 256>>>(embed);
    vq_main<<<N / BMT, THREADS, SMEM_TOTAL>>>(input, q_out, diff_out, ind_out);
}

// round 16
// speedup vs baseline: 6.2501x; 6.2501x over previous
#include <cuda_runtime.h>
#include <cuda_bf16.h>
#include <cstdint>

// B=16, T=4096 -> N=65536 tokens, D=64, K=1024
#define D 64
#define K 1024
#define BMT 128          // tokens per CTA
#define CHN 32           // codes per sub-chunk (acc = 16 regs)
#define NCS 32           // 32 sub-chunks; barrier every 4
#define THREADS 256      // 8 warps, all M (16 token rows each)
#define CAP 32           // candidate list capacity per token
#define EPS_C 0.0170f    // >= 2*(2*2^-8+2^-16) + slack

#define BSUB_BYTES  4096             // 32 rows x 128 B
#define OFF_H    0                   // K floats (4 KB)
#define OFF_N2   4096                // ||x||^2 per row (512 B)
#define OFF_CNT  4608                // candidate counts (512 B)
#define OFF_SI   5120                // final index (512 B)
#define OFF_CAND 5632                // 128 x CAP ints (16 KB)
#define OFF_A    22528               // x0 tile (16 KB), 1024-aligned
#define OFF_B    38912               // 2 buffers x 16 KB (4 sub-tiles each)
#define SMEM_TOTAL (OFF_B + 2 * 16384)   // 71680 B -> 3 CTAs/SM

#define SWZ(b) ((b) ^ (((b) >> 3) & 0x70))

__device__ float          g_embedT[K * D];   // [k][d] fp32 (gather + exact eval)
__device__ float          g_h[K];            // 0.5 * ||e_k||^2
__device__ __nv_bfloat16  g_e0[K * D];       // [k][d] bf16 hi split
__device__ int            g_emax_bits = 0;   // max ||e_k|| as float bits

__device__ __forceinline__ void cp16(uint32_t s, const void* g) {
    asm volatile("cp.async.cg.shared.global [%0], [%1], 16;" :: "r"(s), "l"(g));
}
#define CP_COMMIT()  asm volatile("cp.async.commit_group;")
#define CP_WAIT0()   asm volatile("cp.async.wait_group 0;")

__device__ __forceinline__ void ldsm4(uint32_t r[4], uint32_t addr) {
    asm volatile("ldmatrix.sync.aligned.m8n8.x4.shared.b16 {%0,%1,%2,%3}, [%4];"
        : "=r"(r[0]), "=r"(r[1]), "=r"(r[2]), "=r"(r[3]) : "r"(addr));
}
__device__ __forceinline__ void mma16816(float c[4], const uint32_t a[4],
                                         uint32_t b0, uint32_t b1) {
    asm volatile("mma.sync.aligned.m16n8k16.row.col.f32.bf16.bf16.f32 "
        "{%0,%1,%2,%3}, {%4,%5,%6,%7}, {%8,%9}, {%0,%1,%2,%3};"
        : "+f"(c[0]), "+f"(c[1]), "+f"(c[2]), "+f"(c[3])
        : "r"(a[0]), "r"(a[1]), "r"(a[2]), "r"(a[3]), "r"(b0), "r"(b1));
}
__device__ __forceinline__ uint32_t pack_bf16x2(__nv_bfloat16 lo, __nv_bfloat16 hi) {
    return (uint32_t)__bfloat16_as_ushort(lo) | ((uint32_t)__bfloat16_as_ushort(hi) << 16);
}

// ------------- prep: hi split [k][d], transpose, norms, max-norm -------------
__global__ void vq_prep(const float* __restrict__ embed) {
    int i = blockIdx.x * blockDim.x + threadIdx.x;
    if (i < K * D) {
        int k = i >> 6;
        int d = i & 63;
        float v = embed[d * K + k];
        g_embedT[i] = v;
        g_e0[i] = __float2bfloat16(v);
    }
    if (i < K) {
        float s = 0.f;
        #pragma unroll
        for (int d = 0; d < D; d++) {
            float v = embed[d * K + i];
            s = fmaf(v, v, s);
        }
        g_h[i] = 0.5f * s;
        atomicMax(&g_emax_bits, __float_as_int(sqrtf(s)));
    }
}

__device__ __forceinline__ float score_exact(const float4* x4, int k, const float* hs) {
    const float4* e4 = (const float4*)(g_embedT + k * D);
    float dot = 0.f;
    #pragma unroll
    for (int i = 0; i < 16; i++) {
        float4 a = x4[i], b = e4[i];
        dot = fmaf(a.x, b.x, dot);
        dot = fmaf(a.y, b.y, dot);
        dot = fmaf(a.z, b.z, dot);
        dot = fmaf(a.w, b.w, dot);
    }
    return hs[k] - dot;
}

// ------------- main: hi-split HMMA + streaming prune + exact verify -------------
__global__ __launch_bounds__(THREADS, 3)
void vq_main(const float* __restrict__ input,
             float* __restrict__ q_out,
             float* __restrict__ diff_out,
             float* __restrict__ ind_out) {
    extern __shared__ char smem[];
    const uint32_t sb = (uint32_t)__cvta_generic_to_shared(smem);
    float* hs   = (float*)(smem + OFF_H);
    float* n2   = (float*)(smem + OFF_N2);
    int*   cnt  = (int*)(smem + OFF_CNT);
    int*   s_ix = (int*)(smem + OFF_SI);
    int*   cand = (int*)(smem + OFF_CAND);

    const int tid  = threadIdx.x;
    const int wid  = tid >> 5;     // 0..7 : token rows 16*wid
    const int lane = tid & 31;
    const int n0   = blockIdx.x * BMT;

    if (tid < BMT) cnt[tid] = 0;

    // ---- prologue: x -> bf16 hi tile (SW128) + ||x||^2 via shuffle reduce ----
    const float4* in4 = reinterpret_cast<const float4*>(input + (size_t)n0 * D);
    #pragma unroll
    for (int t = 0; t < 8; t++) {
        int idx = t * THREADS + tid;       // 0..2047 float4
        float4 v = in4[idx];
        int row = idx >> 4;
        int c   = (idx & 15) << 2;
        float p = v.x * v.x + v.y * v.y + v.z * v.z + v.w * v.w;
        #pragma unroll
        for (int m = 1; m <= 8; m <<= 1)
            p += __shfl_xor_sync(0xffffffffu, p, m);   // 16-lane group sum
        if ((tid & 15) == 0) n2[row] = p;
        uint32_t off = SWZ((uint32_t)(row * 128 + c * 2));
        *(uint32_t*)(smem + OFF_A + off)     = pack_bf16x2(__float2bfloat16(v.x), __float2bfloat16(v.y));
        *(uint32_t*)(smem + OFF_A + off + 4) = pack_bf16x2(__float2bfloat16(v.z), __float2bfloat16(v.w));
    }
    #pragma unroll
    for (int t = tid; t < K; t += THREADS) hs[t] = g_h[t];

    // ---- prefetch codes 0..127 (4 sub-tiles): 1024 granules ----
    #pragma unroll
    for (int i = 0; i < 4; i++) {
        int idx = i * THREADS + tid;
        int row = idx >> 3, g = idx & 7;
        cp16(sb + OFF_B + (uint32_t)((row >> 5) * BSUB_BYTES)
                 + SWZ((uint32_t)((row & 31) * 128 + g * 16)),
             g_e0 + (size_t)row * 64 + g * 8);
    }
    CP_COMMIT();

    const float emax = __int_as_float(g_emax_bits);

    const int l7      = lane & 7;
    const int aRowSel = ((lane >> 3) & 1) << 3;
    const int aKSel   = (lane >> 4) << 4;
    const int bRowSel = (lane >> 4) << 3;
    const int bKSel   = ((lane >> 3) & 1) << 4;

    __syncthreads();   // A tile + hs + n2 visible

    // ---- A fragments (chunk-invariant, 16 regs) ----
    uint32_t afr[4][4];
    #pragma unroll
    for (int ks = 0; ks < 4; ks++)
        ldsm4(afr[ks], sb + (uint32_t)OFF_A
            + SWZ((uint32_t)((wid * 16 + aRowSel + l7) * 128 + ks * 32 + aKSel)));

    const int row0 = wid * 16 + (lane >> 2);
    const int row1 = row0 + 8;
    const float eps0 = EPS_C * sqrtf(n2[row0]) * emax;
    const float eps1 = EPS_C * sqrtf(n2[row1]) * emax;

    float rb0 = 3.4e38f, rb1 = 3.4e38f;   // running prefix min per row
    float th0 = 3.4e38f, th1 = 3.4e38f;   // lagged thresholds

    for (int cs = 0; cs < NCS; cs++) {
        if ((cs & 3) == 0) {
            CP_WAIT0();
            __syncthreads();   // staged; everyone done with the other buffer
            if (cs + 4 < NCS) {
                int kb = (cs + 4) * CHN;
                uint32_t bufo = (uint32_t)(OFF_B + (((cs >> 2) + 1) & 1) * 16384);
                #pragma unroll
                for (int i = 0; i < 4; i++) {
                    int idx = i * THREADS + tid;
                    int row = idx >> 3, g = idx & 7;
                    cp16(sb + bufo + (uint32_t)((row >> 5) * BSUB_BYTES)
                             + SWZ((uint32_t)((row & 31) * 128 + g * 16)),
                         g_e0 + (size_t)(kb + row) * 64 + g * 8);
                }
                CP_COMMIT();
            }
        }

        const uint32_t bbase = sb + (uint32_t)(OFF_B + ((cs >> 2) & 1) * 16384
                                               + (cs & 3) * BSUB_BYTES);

        float acc[4][4];
        #pragma unroll
        for (int j = 0; j < 4; j++)
            #pragma unroll
            for (int q = 0; q < 4; q++) acc[j][q] = 0.f;

        #pragma unroll
        for (int ks = 0; ks < 4; ks++) {
            uint32_t bf[2][4];
            #pragma unroll
            for (int jj = 0; jj < 2; jj++)
                ldsm4(bf[jj], bbase
                    + SWZ((uint32_t)((jj * 16 + bRowSel + l7) * 128 + ks * 32 + bKSel)));
            #pragma unroll
            for (int jj = 0; jj < 2; jj++) {
                mma16816(acc[jj * 2 + 0], afr[ks], bf[jj][0], bf[jj][1]);
                mma16816(acc[jj * 2 + 1], afr[ks], bf[jj][2], bf[jj][3]);
            }
        }

        float m0 = 3.4e38f, m1 = 3.4e38f;
        if (cs == 0) {
            #pragma unroll
            for (int j = 0; j < 4; j++) {
                int k0 = j * 8 + (lane & 3) * 2;
                float2 hv = *(const float2*)&hs[k0];
                acc[j][0] = hv.x - acc[j][0];
                acc[j][1] = hv.y - acc[j][1];
                acc[j][2] = hv.x - acc[j][2];
                acc[j][3] = hv.y - acc[j][3];
                m0 = fminf(m0, fminf(acc[j][0], acc[j][1]));
                m1 = fminf(m1, fminf(acc[j][2], acc[j][3]));
            }
            #pragma unroll
            for (int m = 1; m <= 2; m <<= 1) {
                m0 = fminf(m0, __shfl_xor_sync(0xffffffffu, m0, m));
                m1 = fminf(m1, __shfl_xor_sync(0xffffffffu, m1, m));
            }
            rb0 = m0; rb1 = m1;
            th0 = rb0 + eps0; th1 = rb1 + eps1;
            #pragma unroll
            for (int j = 0; j < 4; j++) {
                int k0 = j * 8 + (lane & 3) * 2;
                if (acc[j][0] < th0) { int p = atomicAdd(&cnt[row0], 1); if (p < CAP) cand[row0 * CAP + p] = k0; }
                if (acc[j][1] < th0) { int p = atomicAdd(&cnt[row0], 1); if (p < CAP) cand[row0 * CAP + p] = k0 + 1; }
                if (acc[j][2] < th1) { int p = atomicAdd(&cnt[row1], 1); if (p < CAP) cand[row1 * CAP + p] = k0; }
                if (acc[j][3] < th1) { int p = atomicAdd(&cnt[row1], 1); if (p < CAP) cand[row1 * CAP + p] = k0 + 1; }
            }
        } else {
            // fused: collect with lagged threshold (prefix >= final -> superset)
            #pragma unroll
            for (int j = 0; j < 4; j++) {
                int k0 = cs * CHN + j * 8 + (lane & 3) * 2;
                float2 hv = *(const float2*)&hs[k0];
                float s0 = hv.x - acc[j][0];
                float s1 = hv.y - acc[j][1];
                float s2 = hv.x - acc[j][2];
                float s3 = hv.y - acc[j][3];
                m0 = fminf(m0, fminf(s0, s1));
                m1 = fminf(m1, fminf(s2, s3));
                if (s0 < th0) { int p = atomicAdd(&cnt[row0], 1); if (p < CAP) cand[row0 * CAP + p] = k0; }
                if (s1 < th0) { int p = atomicAdd(&cnt[row0], 1); if (p < CAP) cand[row0 * CAP + p] = k0 + 1; }
                if (s2 < th1) { int p = atomicAdd(&cnt[row1], 1); if (p < CAP) cand[row1 * CAP + p] = k0; }
                if (s3 < th1) { int p = atomicAdd(&cnt[row1], 1); if (p < CAP) cand[row1 * CAP + p] = k0 + 1; }
            }
            #pragma unroll
            for (int m = 1; m <= 2; m <<= 1) {
                m0 = fminf(m0, __shfl_xor_sync(0xffffffffu, m0, m));
                m1 = fminf(m1, __shfl_xor_sync(0xffffffffu, m1, m));
            }
            rb0 = fminf(rb0, m0);
            rb1 = fminf(rb1, m1);
            th0 = rb0 + eps0;
            th1 = rb1 + eps1;
        }
    }

    __syncthreads();

    // ---- exact verification: fp32 re-eval of candidates per token ----
    if (tid < BMT) {
        int row = tid;
        const float4* x4 = (const float4*)(input + (size_t)(n0 + row) * D);
        int n = cnt[row];
        float bsv = 3.4e38f;
        int   bix = 0;
        if (n <= CAP) {
            for (int j = 0; j < n; j++) {
                int k = cand[row * CAP + j];
                float s = score_exact(x4, k, hs);
                if (s < bsv || (s == bsv && k < bix)) { bsv = s; bix = k; }
            }
        } else {
            for (int k = 0; k < K; k++) {   // overflow fallback: exact scan
                float s = score_exact(x4, k, hs);
                if (s < bsv) { bsv = s; bix = k; }
            }
        }
        s_ix[row] = bix;
        if (ind_out) ind_out[n0 + row] = (float)bix;
    }
    __syncthreads();

    // ---- gather quantize + diff (coalesced float4) ----
    #pragma unroll
    for (int t = 0; t < 8; t++) {
        int idx = t * THREADS + tid;
        int row = idx >> 4;
        int cc  = (idx & 15) << 2;
        int kq  = s_ix[row];
        float4 q = *(const float4*)(g_embedT + kq * D + cc);
        float4 x = in4[idx];
        size_t o = (size_t)(n0 + row) * D + cc;
        *reinterpret_cast<float4*>(&q_out[o]) = q;
        if (diff_out) {
            float4 df;
            df.x = (q.x - x.x) * (q.x - x.x);
            df.y = (q.y - x.y) * (q.y - x.y);
            df.z = (q.z - x.z) * (q.z - x.z);
            df.w = (q.w - x.w) * (q.w - x.w);
            *reinterpret_cast<float4*>(&diff_out[o]) = df;
        }
    }
}

extern "C" void kernel_launch(void* const* d_in, const int* in_sizes, int n_in,
                              void* d_out, int out_size) {
    const float* input = (const float*)d_in[0];   // [B,T,D] fp32
    const float* embed = (const float*)d_in[1];   // [D,K]   fp32

    const int N = in_sizes[0] / D;
    const long nd = (long)N * D;

    float* out = (float*)d_out;
    float* q_out    = out;
    float* diff_out = nullptr;
    float* ind_out  = nullptr;
    if ((long)out_size >= 2 * nd + N) { diff_out = out + nd; ind_out = out + 2 * nd; }
    else if ((long)out_size >= 2 * nd) { diff_out = out + nd; }

    cudaFuncSetAttribute(vq_main, cudaFuncAttributeMaxDynamicSharedMemorySize, SMEM_TOTAL);

    vq_prep<<<(K * D + 255) / 256, 256>>>(embed);
    vq_main<<<N / BMT, THREADS, SMEM_TOTAL>>>(input, q_out, diff_out, ind_out);
}

// round 17
// speedup vs baseline: 9.2099x; 1.4736x over previous
#include <cuda_runtime.h>
#include <cuda_bf16.h>
#include <cstdint>

// B=16, T=4096 -> N=65536 tokens, D=64, K=1024
#define D 64
#define K 1024
#define BMT 128          // tokens per CTA
#define CHN 128          // codes per chunk
#define NCHUNK 8         // single pass
#define THREADS 256      // 8 warps, all M (16 token rows each)
#define CAP 32           // candidate list capacity per token
#define EPS_C 0.0170f    // >= 2*(2*2^-8+2^-16) + slack

#define TILE_BYTES 16384             // 128 rows x 128 B bf16, SW128
#define OFF_H    0                   // K floats (4 KB)
#define OFF_N2   4096                // ||x||^2 per row (512 B)
#define OFF_CNT  4608                // candidate counts (512 B)
#define OFF_SI   5120                // final index (512 B)
#define OFF_CAND 5632                // 128 x CAP ints (16 KB)
#define OFF_A    22528               // x0 tile (16 KB), 1024-aligned
#define OFF_B    38912               // 2 x 16 KB B buffers
#define SMEM_TOTAL (OFF_B + 2 * TILE_BYTES)   // 71680 -> 2 CTAs/SM

#define SWZ(b) ((b) ^ (((b) >> 3) & 0x70))

__device__ float          g_embedT[K * D];   // [k][d] fp32 (gather + exact eval)
__device__ float          g_h[K];            // 0.5 * ||e_k||^2
__device__ __nv_bfloat16  g_e0[K * D];       // [k][d] bf16 hi split
__device__ int            g_emax_bits = 0;   // max ||e_k|| as float bits

__device__ __forceinline__ void cp16(uint32_t s, const void* g) {
    asm volatile("cp.async.cg.shared.global [%0], [%1], 16;" :: "r"(s), "l"(g));
}
#define CP_COMMIT()  asm volatile("cp.async.commit_group;")
#define CP_WAIT0()   asm volatile("cp.async.wait_group 0;")

__device__ __forceinline__ void ldsm4(uint32_t r[4], uint32_t addr) {
    asm volatile("ldmatrix.sync.aligned.m8n8.x4.shared.b16 {%0,%1,%2,%3}, [%4];"
        : "=r"(r[0]), "=r"(r[1]), "=r"(r[2]), "=r"(r[3]) : "r"(addr));
}
__device__ __forceinline__ void mma16816(float c[4], const uint32_t a[4],
                                         uint32_t b0, uint32_t b1) {
    asm volatile("mma.sync.aligned.m16n8k16.row.col.f32.bf16.bf16.f32 "
        "{%0,%1,%2,%3}, {%4,%5,%6,%7}, {%8,%9}, {%0,%1,%2,%3};"
        : "+f"(c[0]), "+f"(c[1]), "+f"(c[2]), "+f"(c[3])
        : "r"(a[0]), "r"(a[1]), "r"(a[2]), "r"(a[3]), "r"(b0), "r"(b1));
}
__device__ __forceinline__ uint32_t pack_bf16x2(__nv_bfloat16 lo, __nv_bfloat16 hi) {
    return (uint32_t)__bfloat16_as_ushort(lo) | ((uint32_t)__bfloat16_as_ushort(hi) << 16);
}

// ------------- prep: hi split [k][d], transpose, norms, max-norm -------------
__global__ void vq_prep(const float* __restrict__ embed) {
    int i = blockIdx.x * blockDim.x + threadIdx.x;
    if (i < K * D) {
        int k = i >> 6;
        int d = i & 63;
        float v = embed[d * K + k];
        g_embedT[i] = v;
        g_e0[i] = __float2bfloat16(v);
    }
    if (i < K) {
        float s = 0.f;
        #pragma unroll
        for (int d = 0; d < D; d++) {
            float v = embed[d * K + i];
            s = fmaf(v, v, s);
        }
        g_h[i] = 0.5f * s;
        atomicMax(&g_emax_bits, __float_as_int(sqrtf(s)));
    }
}

__device__ __forceinline__ float score_exact(const float4* x4, int k, const float* hs) {
    const float4* e4 = (const float4*)(g_embedT + k * D);
    float dot = 0.f;
    #pragma unroll
    for (int i = 0; i < 16; i++) {
        float4 a = x4[i], b = e4[i];
        dot = fmaf(a.x, b.x, dot);
        dot = fmaf(a.y, b.y, dot);
        dot = fmaf(a.z, b.z, dot);
        dot = fmaf(a.w, b.w, dot);
    }
    return hs[k] - dot;
}

// ------------- main: hi-split HMMA + streaming prune + exact verify -------------
__global__ __launch_bounds__(THREADS, 2)
void vq_main(const float* __restrict__ input,
             float* __restrict__ q_out,
             float* __restrict__ diff_out,
             float* __restrict__ ind_out) {
    extern __shared__ char smem[];
    const uint32_t sb = (uint32_t)__cvta_generic_to_shared(smem);
    float* hs   = (float*)(smem + OFF_H);
    float* n2   = (float*)(smem + OFF_N2);
    int*   cnt  = (int*)(smem + OFF_CNT);
    int*   s_ix = (int*)(smem + OFF_SI);
    int*   cand = (int*)(smem + OFF_CAND);

    const int tid  = threadIdx.x;
    const int wid  = tid >> 5;     // 0..7 : token rows 16*wid
    const int lane = tid & 31;
    const int n0   = blockIdx.x * BMT;

    if (tid < BMT) cnt[tid] = 0;

    // ---- prologue: x -> bf16 hi tile (SW128) + ||x||^2 via shuffle reduce ----
    const float4* in4 = reinterpret_cast<const float4*>(input + (size_t)n0 * D);
    #pragma unroll
    for (int t = 0; t < 8; t++) {
        int idx = t * THREADS + tid;       // 0..2047 float4
        float4 v = in4[idx];
        int row = idx >> 4;
        int c   = (idx & 15) << 2;
        float p = v.x * v.x + v.y * v.y + v.z * v.z + v.w * v.w;
        #pragma unroll
        for (int m = 1; m <= 8; m <<= 1)
            p += __shfl_xor_sync(0xffffffffu, p, m);   // 16-lane group sum
        if ((tid & 15) == 0) n2[row] = p;
        uint32_t off = SWZ((uint32_t)(row * 128 + c * 2));
        *(uint32_t*)(smem + OFF_A + off)     = pack_bf16x2(__float2bfloat16(v.x), __float2bfloat16(v.y));
        *(uint32_t*)(smem + OFF_A + off + 4) = pack_bf16x2(__float2bfloat16(v.z), __float2bfloat16(v.w));
    }
    #pragma unroll
    for (int t = tid; t < K; t += THREADS) hs[t] = g_h[t];

    // ---- prefetch B chunk 0: 128 rows x 8 granules = 1024 ----
    #pragma unroll
    for (int i = 0; i < 4; i++) {
        int idx = i * THREADS + tid;
        int row = idx >> 3, g = idx & 7;
        cp16(sb + OFF_B + SWZ((uint32_t)(row * 128 + g * 16)),
             g_e0 + (size_t)row * 64 + g * 8);
    }
    CP_COMMIT();

    const float emax = __int_as_float(g_emax_bits);

    const int l7      = lane & 7;
    const int aRowSel = ((lane >> 3) & 1) << 3;
    const int aKSel   = (lane >> 4) << 4;
    const int bRowSel = (lane >> 4) << 3;
    const int bKSel   = ((lane >> 3) & 1) << 4;

    __syncthreads();   // A tile + hs + n2 visible

    // ---- A fragments (chunk-invariant, 16 regs) ----
    uint32_t afr[4][4];
    #pragma unroll
    for (int ks = 0; ks < 4; ks++)
        ldsm4(afr[ks], sb + (uint32_t)OFF_A
            + SWZ((uint32_t)((wid * 16 + aRowSel + l7) * 128 + ks * 32 + aKSel)));

    const int row0 = wid * 16 + (lane >> 2);
    const int row1 = row0 + 8;
    const float eps0 = EPS_C * sqrtf(n2[row0]) * emax;
    const float eps1 = EPS_C * sqrtf(n2[row1]) * emax;

    float rb0 = 3.4e38f, rb1 = 3.4e38f;   // running prefix min per row
    float th0 = 3.4e38f, th1 = 3.4e38f;   // thresholds (lag within chunk loop)

    for (int cs = 0; cs < NCHUNK; cs++) {
        CP_WAIT0();
        __syncthreads();   // chunk staged; everyone done with the other buffer

        if (cs + 1 < NCHUNK) {
            int kb = (cs + 1) * CHN;
            uint32_t bufo = (uint32_t)(OFF_B + ((cs + 1) & 1) * TILE_BYTES);
            #pragma unroll
            for (int i = 0; i < 4; i++) {
                int idx = i * THREADS + tid;
                int row = idx >> 3, g = idx & 7;
                cp16(sb + bufo + SWZ((uint32_t)(row * 128 + g * 16)),
                     g_e0 + (size_t)(kb + row) * 64 + g * 8);
            }
            CP_COMMIT();
        }

        const uint32_t bbase = sb + (uint32_t)(OFF_B + (cs & 1) * TILE_BYTES);

        float acc[16][4];
        #pragma unroll
        for (int j = 0; j < 16; j++)
            #pragma unroll
            for (int q = 0; q < 4; q++) acc[j][q] = 0.f;

        #pragma unroll
        for (int ks = 0; ks < 4; ks++) {
            uint32_t bf[8][4];
            #pragma unroll
            for (int jj = 0; jj < 8; jj++)
                ldsm4(bf[jj], bbase
                    + SWZ((uint32_t)((jj * 16 + bRowSel + l7) * 128 + ks * 32 + bKSel)));
            #pragma unroll
            for (int jj = 0; jj < 8; jj++) {
                mma16816(acc[jj * 2 + 0], afr[ks], bf[jj][0], bf[jj][1]);
                mma16816(acc[jj * 2 + 1], afr[ks], bf[jj][2], bf[jj][3]);
            }
        }

        float m0 = 3.4e38f, m1 = 3.4e38f;
        if (cs == 0) {
            // two-pass for chunk 0 (no threshold yet)
            #pragma unroll
            for (int j = 0; j < 16; j++) {
                int k0 = j * 8 + (lane & 3) * 2;
                float2 hv = *(const float2*)&hs[k0];
                acc[j][0] = hv.x - acc[j][0];
                acc[j][1] = hv.y - acc[j][1];
                acc[j][2] = hv.x - acc[j][2];
                acc[j][3] = hv.y - acc[j][3];
                m0 = fminf(m0, fminf(acc[j][0], acc[j][1]));
                m1 = fminf(m1, fminf(acc[j][2], acc[j][3]));
            }
            #pragma unroll
            for (int m = 1; m <= 2; m <<= 1) {
                m0 = fminf(m0, __shfl_xor_sync(0xffffffffu, m0, m));
                m1 = fminf(m1, __shfl_xor_sync(0xffffffffu, m1, m));
            }
            rb0 = m0; rb1 = m1;
            th0 = rb0 + eps0; th1 = rb1 + eps1;
            #pragma unroll
            for (int j = 0; j < 16; j++) {
                int k0 = j * 8 + (lane & 3) * 2;
                float p0 = fminf(acc[j][0], acc[j][1]);
                float p1 = fminf(acc[j][2], acc[j][3]);
                if (p0 < th0) {
                    if (acc[j][0] < th0) { int p = atomicAdd(&cnt[row0], 1); if (p < CAP) cand[row0 * CAP + p] = k0; }
                    if (acc[j][1] < th0) { int p = atomicAdd(&cnt[row0], 1); if (p < CAP) cand[row0 * CAP + p] = k0 + 1; }
                }
                if (p1 < th1) {
                    if (acc[j][2] < th1) { int p = atomicAdd(&cnt[row1], 1); if (p < CAP) cand[row1 * CAP + p] = k0; }
                    if (acc[j][3] < th1) { int p = atomicAdd(&cnt[row1], 1); if (p < CAP) cand[row1 * CAP + p] = k0 + 1; }
                }
            }
        } else {
            // fused pass: paired min feeds BOTH prefix-min and the collect guard
            #pragma unroll
            for (int j = 0; j < 16; j++) {
                int k0 = cs * CHN + j * 8 + (lane & 3) * 2;
                float2 hv = *(const float2*)&hs[k0];
                float s0 = hv.x - acc[j][0];
                float s1 = hv.y - acc[j][1];
                float s2 = hv.x - acc[j][2];
                float s3 = hv.y - acc[j][3];
                float p0 = fminf(s0, s1);
                float p1 = fminf(s2, s3);
                m0 = fminf(m0, p0);
                m1 = fminf(m1, p1);
                if (p0 < th0) {
                    if (s0 < th0) { int p = atomicAdd(&cnt[row0], 1); if (p < CAP) cand[row0 * CAP + p] = k0; }
                    if (s1 < th0) { int p = atomicAdd(&cnt[row0], 1); if (p < CAP) cand[row0 * CAP + p] = k0 + 1; }
                }
                if (p1 < th1) {
                    if (s2 < th1) { int p = atomicAdd(&cnt[row1], 1); if (p < CAP) cand[row1 * CAP + p] = k0; }
                    if (s3 < th1) { int p = atomicAdd(&cnt[row1], 1); if (p < CAP) cand[row1 * CAP + p] = k0 + 1; }
                }
            }
            #pragma unroll
            for (int m = 1; m <= 2; m <<= 1) {
                m0 = fminf(m0, __shfl_xor_sync(0xffffffffu, m0, m));
                m1 = fminf(m1, __shfl_xor_sync(0xffffffffu, m1, m));
            }
            rb0 = fminf(rb0, m0);
            rb1 = fminf(rb1, m1);
            th0 = rb0 + eps0;
            th1 = rb1 + eps1;
        }
        // no bottom sync: top-of-loop sync of iter cs+1 protects buffer reuse
    }

    __syncthreads();

    // ---- exact verification: fp32 re-eval of candidates per token ----
    if (tid < BMT) {
        int row = tid;
        const float4* x4 = (const float4*)(input + (size_t)(n0 + row) * D);
        int n = cnt[row];
        float bsv = 3.4e38f;
        int   bix = 0;
        if (n <= CAP) {
            for (int j = 0; j < n; j++) {
                int k = cand[row * CAP + j];
                float s = score_exact(x4, k, hs);
                if (s < bsv || (s == bsv && k < bix)) { bsv = s; bix = k; }
            }
        } else {
            for (int k = 0; k < K; k++) {   // overflow fallback: exact scan
                float s = score_exact(x4, k, hs);
                if (s < bsv) { bsv = s; bix = k; }
            }
        }
        s_ix[row] = bix;
        if (ind_out) ind_out[n0 + row] = (float)bix;
    }
    __syncthreads();

    // ---- gather quantize + diff (coalesced float4) ----
    #pragma unroll
    for (int t = 0; t < 8; t++) {
        int idx = t * THREADS + tid;
        int row = idx >> 4;
        int cc  = (idx & 15) << 2;
        int kq  = s_ix[row];
        float4 q = *(const float4*)(g_embedT + kq * D + cc);
        float4 x = in4[idx];
        size_t o = (size_t)(n0 + row) * D + cc;
        *reinterpret_cast<float4*>(&q_out[o]) = q;
        if (diff_out) {
            float4 df;
            df.x = (q.x - x.x) * (q.x - x.x);
            df.y = (q.y - x.y) * (q.y - x.y);
            df.z = (q.z - x.z) * (q.z - x.z);
            df.w = (q.w - x.w) * (q.w - x.w);
            *reinterpret_cast<float4*>(&diff_out[o]) = df;
        }
    }
}

extern "C" void kernel_launch(void* const* d_in, const int* in_sizes, int n_in,
                              void* d_out, int out_size) {
    const float* input = (const float*)d_in[0];   // [B,T,D] fp32
    const float* embed = (const float*)d_in[1];   // [D,K]   fp32

    const int N = in_sizes[0] / D;
    const long nd = (long)N * D;

    float* out = (float*)d_out;
    float* q_out    = out;
    float* diff_out = nullptr;
    float* ind_out  = nullptr;
    if ((long)out_size >= 2 * nd + N) { diff_out = out + nd; ind_out = out + 2 * nd; }
    else if ((long)out_size >= 2 * nd) { diff_out = out + nd; }

    cudaFuncSetAttribute(vq_main, cudaFuncAttributeMaxDynamicSharedMemorySize, SMEM_TOTAL);

    vq_prep<<<(K * D + 255) / 256, 256>>>(embed);
    vq_main<<<N / BMT, THREADS, SMEM_TOTAL>>>(input, q_out, diff_out, ind_out);
}